// round 8
// baseline (speedup 1.0000x reference)
#include <cuda_runtime.h>
#include <cstdint>

#define ALPHA 16.0f
#define DDIM  1024
#define MROWS 16384   // B*S

// ---------------- scratch (no cudaMalloc allowed) ----------------
__device__ float g_E[DDIM * DDIM];   // Et[o][d] : TRANSPOSED, tf32-pre-rounded

// ---------------- helpers ----------------
__device__ __forceinline__ uint32_t smem_u32(const void* p) {
    uint32_t a;
    asm("{ .reg .u64 t; cvta.to.shared.u64 t, %1; cvt.u32.u64 %0, t; }" : "=r"(a) : "l"(p));
    return a;
}
__device__ __forceinline__ float to_tf32_f(float v) {
    asm("cvt.rna.tf32.f32 %0, %1;" : "=f"(v) : "f"(v));
    return v;
}
__device__ __forceinline__ void cp16(void* dst_smem, const void* src) {
    uint32_t d = smem_u32(dst_smem);
    asm volatile("cp.async.cg.shared.global [%0], [%1], 16;" :: "r"(d), "l"(src) : "memory");
}
#define CP_COMMIT()  asm volatile("cp.async.commit_group;" ::: "memory")
#define CP_WAIT(n)   asm volatile("cp.async.wait_group %0;" :: "n"(n) : "memory")

// A fed as raw fp32 bits: HMMA.TF32 truncates trailing mantissa (cuBLAS-style).
__device__ __forceinline__ void mma_tf32(float* c, const uint32_t* a, const uint32_t* b) {
    asm volatile(
        "mma.sync.aligned.m16n8k8.row.col.f32.tf32.tf32.f32 "
        "{%0,%1,%2,%3}, {%4,%5,%6,%7}, {%8,%9}, {%0,%1,%2,%3};"
        : "+f"(c[0]), "+f"(c[1]), "+f"(c[2]), "+f"(c[3])
        : "r"(a[0]), "r"(a[1]), "r"(a[2]), "r"(a[3]), "r"(b[0]), "r"(b[1]));
}

// ---------------------------------------------------------------------------
// Kernel 1 (fused): per 64x64 tile of Et, fold TT cores (tiny, redundant per
// block), emit Et[o][d] = tf32( W[o][d] + ALPHA * Left[d,:]@Right[:,o] ).
// Both the W read and the Et write are coalesced over d (o-major layout).
// ---------------------------------------------------------------------------
__global__ __launch_bounds__(256)
void build_E_fused(const float* __restrict__ W,
                   const float* __restrict__ c0, const float* __restrict__ c1,
                   const float* __restrict__ c2, const float* __restrict__ c3,
                   const float* __restrict__ c4, const float* __restrict__ c5) {
    __shared__ float C0[64], C1[1024], C2[512], C3[512], C4[1024], C5[64];
    __shared__ float P[1024], S1[1024];
    __shared__ float Lt[64 * 8], Rt[8 * 64];
    const int t  = threadIdx.x;
    const int bd = blockIdx.x;    // d-tile (64 wide)
    const int bo = blockIdx.y;    // o-tile (64 wide)

    for (int i = t; i < 64;   i += 256) C0[i] = c0[i];
    for (int i = t; i < 1024; i += 256) C1[i] = c1[i];
    for (int i = t; i < 512;  i += 256) C2[i] = c2[i];
    for (int i = t; i < 512;  i += 256) C3[i] = c3[i];
    for (int i = t; i < 1024; i += 256) C4[i] = c4[i];
    for (int i = t; i < 64;   i += 256) C5[i] = c5[i];
    __syncthreads();

    #pragma unroll
    for (int p = 0; p < 4; p++) {
        int i = t + p * 256;
        int b = i & 7, m2 = (i >> 3) & 15, m1 = i >> 7;
        float s = 0.f;
        #pragma unroll
        for (int a = 0; a < 8; a++) s += C0[m1 * 8 + a] * C1[(a * 16 + m2) * 8 + b];
        P[i] = s;
    }
    #pragma unroll
    for (int p = 0; p < 4; p++) {
        int i = t + p * 256;
        int n3 = i & 7, n2 = (i >> 3) & 15, e = i >> 7;
        float s = 0.f;
        #pragma unroll
        for (int f = 0; f < 8; f++) s += C4[(e * 16 + n2) * 8 + f] * C5[f * 8 + n3];
        S1[i] = s;
    }
    __syncthreads();

    #pragma unroll
    for (int p = 0; p < 2; p++) {   // Left rows for this d-tile: 64x8
        int j = t + p * 256;
        int di = j >> 3, c = j & 7;
        int d = bd * 64 + di;
        int m1 = d & 7, m2 = (d >> 3) & 15, m3 = d >> 7;
        float s = 0.f;
        #pragma unroll
        for (int b = 0; b < 8; b++) s += P[(m1 * 16 + m2) * 8 + b] * C2[(b * 8 + m3) * 8 + c];
        Lt[di * 8 + c] = s;
    }
    #pragma unroll
    for (int p = 0; p < 2; p++) {   // Right cols for this o-tile: 8x64
        int j = t + p * 256;
        int c = j >> 6, oi = j & 63;
        int o = bo * 64 + oi;
        int n3 = o & 7, n2 = (o >> 3) & 15, n1 = o >> 7;
        float s = 0.f;
        #pragma unroll
        for (int e = 0; e < 8; e++) s += C3[(c * 8 + n1) * 8 + e] * S1[(e * 16 + n2) * 8 + n3];
        Rt[c * 64 + oi] = s;
    }
    __syncthreads();

    #pragma unroll
    for (int p = 0; p < 16; p++) {
        int j = t + p * 256;
        int di = j & 63, oi = j >> 6;        // di fastest -> coalesced
        float s = 0.f;
        #pragma unroll
        for (int c = 0; c < 8; c++) s += Lt[di * 8 + c] * Rt[c * 64 + oi];
        size_t idx = (size_t)(bo * 64 + oi) * 1024 + bd * 64 + di;
        g_E[idx] = to_tf32_f(W[idx] + ALPHA * s);
    }
}

// ---------------------------------------------------------------------------
// Kernel 2: tf32 mma.sync GEMM. C[16384,1024] = X @ Et^T + bias.
// BM=128, BN=128, BK=32. 256 threads, 8 warps (4x2), warp tile 32x64.
// 2 CTAs/SM. 3-stage cp.async pipeline, one sync per chunk.
// k-permutation sigma=[0,2,4,6,1,3,5,7]: fragment slots (tig,tig+4) map to
// smem k = (2tig, 2tig+1) -> ALL fragment loads are LDS.64 (float2).
// Both tiles [128][36]: stride 36 -> every bank hit exactly 2x per LDS.64.
// ---------------------------------------------------------------------------
#define TSTRIDE 36
#define T_STG   (128 * TSTRIDE)
#define STAGES  3
#define NCHUNK  32

__global__ __launch_bounds__(256, 2)
void gemm_tf32(const float* __restrict__ X, const float* __restrict__ bias,
               float* __restrict__ out) {
    extern __shared__ float sm[];
    float* As = sm;                          // STAGES x [128][36]
    float* Bs = sm + STAGES * T_STG;         // STAGES x [128][36] (Et rows = n)

    const int t    = threadIdx.x;
    const int wid  = t >> 5;
    const int lane = t & 31;
    const int g    = lane >> 2;     // 0..7
    const int tig  = lane & 3;      // 0..3
    const int wm   = wid >> 1;      // 0..3  (32-row band)
    const int wn   = wid & 1;       // 0..1  (64-col band)
    const int bx   = blockIdx.x;    // N tile (0..7)
    const int by   = blockIdx.y;    // M tile (0..127)

    const float* Xb = X + (size_t)(by * 128) * 1024;
    const float* Eb = g_E + (size_t)(bx * 128) * 1024;   // Et rows o, cols d

    float acc[2][8][4];
    #pragma unroll
    for (int mt = 0; mt < 2; mt++)
        #pragma unroll
        for (int nt = 0; nt < 8; nt++)
            #pragma unroll
            for (int i = 0; i < 4; i++) acc[mt][nt][i] = 0.f;

    auto load_stage = [&](int s, int kc) {
        float* Ad = As + s * T_STG;
        float* Bd = Bs + s * T_STG;
        #pragma unroll
        for (int p = 0; p < 4; p++) {           // A: 128 rows x 32 k
            int qi = t + p * 256;
            int row = qi >> 3, quad = qi & 7;
            cp16(Ad + row * TSTRIDE + quad * 4,
                 Xb + (size_t)row * 1024 + kc + quad * 4);
        }
        #pragma unroll
        for (int p = 0; p < 4; p++) {           // B: 128 n-rows x 32 k
            int qi = t + p * 256;
            int row = qi >> 3, quad = qi & 7;
            cp16(Bd + row * TSTRIDE + quad * 4,
                 Eb + (size_t)row * 1024 + kc + quad * 4);
        }
    };

    load_stage(0, 0);  CP_COMMIT();
    load_stage(1, 32); CP_COMMIT();

    for (int c = 0; c < NCHUNK; c++) {
        if (c == NCHUNK - 1) { CP_WAIT(0); } else { CP_WAIT(1); }
        __syncthreads();

        if (c + 2 < NCHUNK) {
            load_stage((c + 2) % STAGES, (c + 2) * 32);
            CP_COMMIT();
        }

        const float* Ab = As + (c % STAGES) * T_STG;
        const float* Bb = Bs + (c % STAGES) * T_STG;

        #pragma unroll
        for (int ks = 0; ks < 4; ks++) {
            const int k0 = ks * 8;
            // A fragments: sigma pairs adjacent -> float2
            uint32_t af[2][4];
            #pragma unroll
            for (int mt = 0; mt < 2; mt++) {
                int m = wm * 32 + mt * 16;
                float2 lo = *(const float2*)(Ab + (m + g)     * TSTRIDE + k0 + 2 * tig);
                float2 hi = *(const float2*)(Ab + (m + g + 8) * TSTRIDE + k0 + 2 * tig);
                af[mt][0] = __float_as_uint(lo.x);   // MMA k-row tig
                af[mt][1] = __float_as_uint(hi.x);
                af[mt][2] = __float_as_uint(lo.y);   // MMA k-row tig+4
                af[mt][3] = __float_as_uint(hi.y);
            }
            #pragma unroll
            for (int nt = 0; nt < 8; nt++) {
                int n = wn * 64 + nt * 8;
                float2 bv = *(const float2*)(Bb + (n + g) * TSTRIDE + k0 + 2 * tig);
                uint32_t bf[2] = { __float_as_uint(bv.x), __float_as_uint(bv.y) };
                mma_tf32(acc[0][nt], af[0], bf);
                mma_tf32(acc[1][nt], af[1], bf);
            }
        }
    }

    // ---- epilogue: bias add, direct stores ----
    #pragma unroll
    for (int mt = 0; mt < 2; mt++) {
        int row0 = by * 128 + wm * 32 + mt * 16 + g;
        #pragma unroll
        for (int nt = 0; nt < 8; nt++) {
            int col = bx * 128 + wn * 64 + nt * 8 + tig * 2;
            float b0 = bias[col], b1 = bias[col + 1];
            float2 v0 = { acc[mt][nt][0] + b0, acc[mt][nt][1] + b1 };
            float2 v1 = { acc[mt][nt][2] + b0, acc[mt][nt][3] + b1 };
            *(float2*)(out + (size_t)row0 * 1024 + col)       = v0;
            *(float2*)(out + (size_t)(row0 + 8) * 1024 + col) = v1;
        }
    }
}

// ---------------------------------------------------------------------------
extern "C" void kernel_launch(void* const* d_in, const int* in_sizes, int n_in,
                              void* d_out, int out_size) {
    const float* x  = (const float*)d_in[0];
    const float* W  = (const float*)d_in[1];
    const float* b  = (const float*)d_in[2];
    const float* c0 = (const float*)d_in[3];
    const float* c1 = (const float*)d_in[4];
    const float* c2 = (const float*)d_in[5];
    const float* c3 = (const float*)d_in[6];
    const float* c4 = (const float*)d_in[7];
    const float* c5 = (const float*)d_in[8];
    float* out = (float*)d_out;

    dim3 bgrid(16, 16);
    build_E_fused<<<bgrid, 256>>>(W, c0, c1, c2, c3, c4, c5);

    const int smem_bytes = STAGES * 2 * T_STG * 4;   // 108 KB/CTA -> 2 CTAs/SM
    cudaFuncSetAttribute(gemm_tf32, cudaFuncAttributeMaxDynamicSharedMemorySize, smem_bytes);
    dim3 grid(8, 128);   // bx fastest: concurrent CTAs share the A band in L2
    gemm_tf32<<<grid, 256, smem_bytes>>>(x, b, out);
}

// round 9
// speedup vs baseline: 1.3142x; 1.3142x over previous
#include <cuda_runtime.h>
#include <cstdint>

#define ALPHA 16.0f
#define DDIM  1024
#define MROWS 16384   // B*S

// ---------------- scratch (no cudaMalloc allowed) ----------------
__device__ float g_E[DDIM * DDIM];   // Et[o][d] : TRANSPOSED, tf32-pre-rounded

// ---------------- helpers ----------------
__device__ __forceinline__ uint32_t smem_u32(const void* p) {
    uint32_t a;
    asm("{ .reg .u64 t; cvta.to.shared.u64 t, %1; cvt.u32.u64 %0, t; }" : "=r"(a) : "l"(p));
    return a;
}
__device__ __forceinline__ float to_tf32_f(float v) {
    asm("cvt.rna.tf32.f32 %0, %1;" : "=f"(v) : "f"(v));
    return v;
}
__device__ __forceinline__ void cp16(void* dst_smem, const void* src) {
    uint32_t d = smem_u32(dst_smem);
    asm volatile("cp.async.cg.shared.global [%0], [%1], 16;" :: "r"(d), "l"(src) : "memory");
}
#define CP_COMMIT()  asm volatile("cp.async.commit_group;" ::: "memory")
#define CP_WAIT(n)   asm volatile("cp.async.wait_group %0;" :: "n"(n) : "memory")

// ldmatrix on tf32 data: pure bit movement, 8x8 tiles of 16B rows (=4 tf32).
__device__ __forceinline__ void ldsm4(uint32_t& r0, uint32_t& r1, uint32_t& r2,
                                      uint32_t& r3, uint32_t addr) {
    asm volatile("ldmatrix.sync.aligned.m8n8.x4.shared.b16 {%0,%1,%2,%3}, [%4];"
                 : "=r"(r0), "=r"(r1), "=r"(r2), "=r"(r3) : "r"(addr));
}

// A fed as raw fp32 bits: HMMA.TF32 truncates trailing mantissa (cuBLAS-style).
__device__ __forceinline__ void mma_tf32(float* c, const uint32_t* a, const uint32_t* b) {
    asm volatile(
        "mma.sync.aligned.m16n8k8.row.col.f32.tf32.tf32.f32 "
        "{%0,%1,%2,%3}, {%4,%5,%6,%7}, {%8,%9}, {%0,%1,%2,%3};"
        : "+f"(c[0]), "+f"(c[1]), "+f"(c[2]), "+f"(c[3])
        : "r"(a[0]), "r"(a[1]), "r"(a[2]), "r"(a[3]), "r"(b[0]), "r"(b[1]));
}

// ---------------------------------------------------------------------------
// Kernel 1 (fused): per 64x64 tile of Et, fold TT cores (tiny, redundant per
// block), emit Et[o][d] = tf32( W[o][d] + ALPHA * Left[d,:]@Right[:,o] ).
// W read and Et write both coalesced over d (o-major layout).
// ---------------------------------------------------------------------------
__global__ __launch_bounds__(256)
void build_E_fused(const float* __restrict__ W,
                   const float* __restrict__ c0, const float* __restrict__ c1,
                   const float* __restrict__ c2, const float* __restrict__ c3,
                   const float* __restrict__ c4, const float* __restrict__ c5) {
    __shared__ float C0[64], C1[1024], C2[512], C3[512], C4[1024], C5[64];
    __shared__ float P[1024], S1[1024];
    __shared__ float Lt[64 * 8], Rt[8 * 64];
    const int t  = threadIdx.x;
    const int bd = blockIdx.x;    // d-tile (64 wide)
    const int bo = blockIdx.y;    // o-tile (64 wide)

    for (int i = t; i < 64;   i += 256) C0[i] = c0[i];
    for (int i = t; i < 1024; i += 256) C1[i] = c1[i];
    for (int i = t; i < 512;  i += 256) C2[i] = c2[i];
    for (int i = t; i < 512;  i += 256) C3[i] = c3[i];
    for (int i = t; i < 1024; i += 256) C4[i] = c4[i];
    for (int i = t; i < 64;   i += 256) C5[i] = c5[i];
    __syncthreads();

    #pragma unroll
    for (int p = 0; p < 4; p++) {
        int i = t + p * 256;
        int b = i & 7, m2 = (i >> 3) & 15, m1 = i >> 7;
        float s = 0.f;
        #pragma unroll
        for (int a = 0; a < 8; a++) s += C0[m1 * 8 + a] * C1[(a * 16 + m2) * 8 + b];
        P[i] = s;
    }
    #pragma unroll
    for (int p = 0; p < 4; p++) {
        int i = t + p * 256;
        int n3 = i & 7, n2 = (i >> 3) & 15, e = i >> 7;
        float s = 0.f;
        #pragma unroll
        for (int f = 0; f < 8; f++) s += C4[(e * 16 + n2) * 8 + f] * C5[f * 8 + n3];
        S1[i] = s;
    }
    __syncthreads();

    #pragma unroll
    for (int p = 0; p < 2; p++) {   // Left rows for this d-tile: 64x8
        int j = t + p * 256;
        int di = j >> 3, c = j & 7;
        int d = bd * 64 + di;
        int m1 = d & 7, m2 = (d >> 3) & 15, m3 = d >> 7;
        float s = 0.f;
        #pragma unroll
        for (int b = 0; b < 8; b++) s += P[(m1 * 16 + m2) * 8 + b] * C2[(b * 8 + m3) * 8 + c];
        Lt[di * 8 + c] = s;
    }
    #pragma unroll
    for (int p = 0; p < 2; p++) {   // Right cols for this o-tile: 8x64
        int j = t + p * 256;
        int c = j >> 6, oi = j & 63;
        int o = bo * 64 + oi;
        int n3 = o & 7, n2 = (o >> 3) & 15, n1 = o >> 7;
        float s = 0.f;
        #pragma unroll
        for (int e = 0; e < 8; e++) s += C3[(c * 8 + n1) * 8 + e] * S1[(e * 16 + n2) * 8 + n3];
        Rt[c * 64 + oi] = s;
    }
    __syncthreads();

    #pragma unroll
    for (int p = 0; p < 16; p++) {
        int j = t + p * 256;
        int di = j & 63, oi = j >> 6;        // di fastest -> coalesced
        float s = 0.f;
        #pragma unroll
        for (int c = 0; c < 8; c++) s += Lt[di * 8 + c] * Rt[c * 64 + oi];
        size_t idx = (size_t)(bo * 64 + oi) * 1024 + bd * 64 + di;
        g_E[idx] = to_tf32_f(W[idx] + ALPHA * s);
    }
}

// ---------------------------------------------------------------------------
// Kernel 2: tf32 mma.sync GEMM via ldmatrix. C[16384,1024] = X @ Et^T + bias.
// BM=128, BN=128, BK=32. 256 threads, 8 warps (4x2), warp tile 32x64.
// 2 CTAs/SM. 3-stage cp.async pipeline, one sync per chunk.
// Fragments gathered with ldmatrix.m8n8.x4.b16 (tf32 = 2 b16): 24 LDSM.x4
// per warp-chunk replace 96 LDS.32. Stride 36 floats -> within each 8-row
// phase, 16B-line bank = 4r mod 32 is a permutation -> conflict-free.
// ---------------------------------------------------------------------------
#define TSTRIDE 36
#define T_STG   (128 * TSTRIDE)
#define STAGES  3
#define NCHUNK  32

__global__ __launch_bounds__(256, 2)
void gemm_tf32(const float* __restrict__ X, const float* __restrict__ bias,
               float* __restrict__ out) {
    extern __shared__ float sm[];
    float* As = sm;                          // STAGES x [128][36]
    float* Bs = sm + STAGES * T_STG;         // STAGES x [128][36] (Et rows = n)

    const int t    = threadIdx.x;
    const int wid  = t >> 5;
    const int lane = t & 31;
    const int g    = lane >> 2;     // 0..7
    const int tig  = lane & 3;      // 0..3
    const int wm   = wid >> 1;      // 0..3  (32-row band)
    const int wn   = wid & 1;       // 0..1  (64-col band)
    const int bx   = blockIdx.x;    // N tile (0..7)
    const int by   = blockIdx.y;    // M tile (0..127)

    const float* Xb = X + (size_t)(by * 128) * 1024;
    const float* Eb = g_E + (size_t)(bx * 128) * 1024;   // Et rows o, cols d

    const uint32_t As_u = smem_u32(As);
    const uint32_t Bs_u = smem_u32(Bs);

    // ldmatrix per-lane row addresses (byte offsets within a stage).
    // A x4 tile order: (rows+0..7,kLo)(rows+8..15,kLo)(rows+0..7,kHi)(rows+8..15,kHi)
    //   lanes 0-15 -> row base+(lane&15), k-lo; lanes 16-31 -> same rows, k-hi.
    uint32_t aoff[2];
    #pragma unroll
    for (int mt = 0; mt < 2; mt++) {
        int row = wm * 32 + mt * 16 + (lane & 15);
        int kh  = (lane >> 4) & 1;              // 0: k0..3, 1: k4..7
        aoff[mt] = (uint32_t)(row * TSTRIDE + kh * 4) * 4u;
    }
    // B x4 tile order: (n+0..7,kLo)(n+0..7,kHi)(n+8..15,kLo)(n+8..15,kHi)
    //   -> regs {b0,b1} for nt=2*q, {b2,b3}... i.e. reg0,1 = n-lo tile frags,
    //      reg2,3 = n-hi tile frags.
    uint32_t boff[4];
    #pragma unroll
    for (int q = 0; q < 4; q++) {
        int row = wn * 64 + q * 16 + ((lane >> 4) & 1) * 8 + (lane & 7);
        int kh  = (lane >> 3) & 1;
        boff[q] = (uint32_t)(row * TSTRIDE + kh * 4) * 4u;
    }

    float acc[2][8][4];
    #pragma unroll
    for (int mt = 0; mt < 2; mt++)
        #pragma unroll
        for (int nt = 0; nt < 8; nt++)
            #pragma unroll
            for (int i = 0; i < 4; i++) acc[mt][nt][i] = 0.f;

    auto load_stage = [&](int s, int kc) {
        float* Ad = As + s * T_STG;
        float* Bd = Bs + s * T_STG;
        #pragma unroll
        for (int p = 0; p < 4; p++) {           // A: 128 rows x 32 k
            int qi = t + p * 256;
            int row = qi >> 3, quad = qi & 7;
            cp16(Ad + row * TSTRIDE + quad * 4,
                 Xb + (size_t)row * 1024 + kc + quad * 4);
        }
        #pragma unroll
        for (int p = 0; p < 4; p++) {           // B: 128 n-rows x 32 k
            int qi = t + p * 256;
            int row = qi >> 3, quad = qi & 7;
            cp16(Bd + row * TSTRIDE + quad * 4,
                 Eb + (size_t)row * 1024 + kc + quad * 4);
        }
    };

    load_stage(0, 0);  CP_COMMIT();
    load_stage(1, 32); CP_COMMIT();

    for (int c = 0; c < NCHUNK; c++) {
        if (c == NCHUNK - 1) { CP_WAIT(0); } else { CP_WAIT(1); }
        __syncthreads();

        if (c + 2 < NCHUNK) {
            load_stage((c + 2) % STAGES, (c + 2) * 32);
            CP_COMMIT();
        }

        const uint32_t aB = As_u + (uint32_t)((c % STAGES) * T_STG) * 4u;
        const uint32_t bB = Bs_u + (uint32_t)((c % STAGES) * T_STG) * 4u;

        #pragma unroll
        for (int ks = 0; ks < 4; ks++) {
            const uint32_t kb = (uint32_t)(ks * 8) * 4u;   // k0 bytes
            uint32_t af[2][4];
            ldsm4(af[0][0], af[0][1], af[0][2], af[0][3], aB + aoff[0] + kb);
            ldsm4(af[1][0], af[1][1], af[1][2], af[1][3], aB + aoff[1] + kb);
            #pragma unroll
            for (int q = 0; q < 4; q++) {
                uint32_t bf[4];
                ldsm4(bf[0], bf[1], bf[2], bf[3], bB + boff[q] + kb);
                mma_tf32(acc[0][2 * q],     af[0], bf);
                mma_tf32(acc[1][2 * q],     af[1], bf);
                mma_tf32(acc[0][2 * q + 1], af[0], bf + 2);
                mma_tf32(acc[1][2 * q + 1], af[1], bf + 2);
            }
        }
    }

    // ---- epilogue: bias add, direct stores ----
    #pragma unroll
    for (int mt = 0; mt < 2; mt++) {
        int row0 = by * 128 + wm * 32 + mt * 16 + g;
        #pragma unroll
        for (int nt = 0; nt < 8; nt++) {
            int col = bx * 128 + wn * 64 + nt * 8 + tig * 2;
            float b0 = bias[col], b1 = bias[col + 1];
            float2 v0 = { acc[mt][nt][0] + b0, acc[mt][nt][1] + b1 };
            float2 v1 = { acc[mt][nt][2] + b0, acc[mt][nt][3] + b1 };
            *(float2*)(out + (size_t)row0 * 1024 + col)       = v0;
            *(float2*)(out + (size_t)(row0 + 8) * 1024 + col) = v1;
        }
    }
}

// ---------------------------------------------------------------------------
extern "C" void kernel_launch(void* const* d_in, const int* in_sizes, int n_in,
                              void* d_out, int out_size) {
    const float* x  = (const float*)d_in[0];
    const float* W  = (const float*)d_in[1];
    const float* b  = (const float*)d_in[2];
    const float* c0 = (const float*)d_in[3];
    const float* c1 = (const float*)d_in[4];
    const float* c2 = (const float*)d_in[5];
    const float* c3 = (const float*)d_in[6];
    const float* c4 = (const float*)d_in[7];
    const float* c5 = (const float*)d_in[8];
    float* out = (float*)d_out;

    dim3 bgrid(16, 16);
    build_E_fused<<<bgrid, 256>>>(W, c0, c1, c2, c3, c4, c5);

    const int smem_bytes = STAGES * 2 * T_STG * 4;   // 108 KB/CTA -> 2 CTAs/SM
    cudaFuncSetAttribute(gemm_tf32, cudaFuncAttributeMaxDynamicSharedMemorySize, smem_bytes);
    dim3 grid(8, 128);   // bx fastest: concurrent CTAs share the A band in L2
    gemm_tf32<<<grid, 256, smem_bytes>>>(x, b, out);
}

// round 10
// speedup vs baseline: 2.0535x; 1.5626x over previous
#include <cuda_runtime.h>
#include <cuda_fp16.h>
#include <cstdint>

#define ALPHA 16.0f
#define DDIM  1024
#define MROWS 16384   // B*S

// ---------------- scratch (no cudaMalloc allowed) ----------------
__device__ __align__(16) __half g_Eh[DDIM * DDIM];    // Et[o][d], fp16(RN)
__device__ __align__(16) __half g_Xh[(size_t)MROWS * DDIM];  // X in fp16(RN)

// ---------------- helpers ----------------
__device__ __forceinline__ uint32_t smem_u32(const void* p) {
    uint32_t a;
    asm("{ .reg .u64 t; cvta.to.shared.u64 t, %1; cvt.u32.u64 %0, t; }" : "=r"(a) : "l"(p));
    return a;
}
__device__ __forceinline__ void cp16(void* dst_smem, const void* src) {
    uint32_t d = smem_u32(dst_smem);
    asm volatile("cp.async.cg.shared.global [%0], [%1], 16;" :: "r"(d), "l"(src) : "memory");
}
#define CP_COMMIT()  asm volatile("cp.async.commit_group;" ::: "memory")
#define CP_WAIT(n)   asm volatile("cp.async.wait_group %0;" :: "n"(n) : "memory")

__device__ __forceinline__ void ldsm4(uint32_t& r0, uint32_t& r1, uint32_t& r2,
                                      uint32_t& r3, uint32_t addr) {
    asm volatile("ldmatrix.sync.aligned.m8n8.x4.shared.b16 {%0,%1,%2,%3}, [%4];"
                 : "=r"(r0), "=r"(r1), "=r"(r2), "=r"(r3) : "r"(addr));
}

__device__ __forceinline__ void mma_f16(float* c, const uint32_t* a, const uint32_t* b) {
    asm volatile(
        "mma.sync.aligned.m16n8k16.row.col.f32.f16.f16.f32 "
        "{%0,%1,%2,%3}, {%4,%5,%6,%7}, {%8,%9}, {%0,%1,%2,%3};"
        : "+f"(c[0]), "+f"(c[1]), "+f"(c[2]), "+f"(c[3])
        : "r"(a[0]), "r"(a[1]), "r"(a[2]), "r"(a[3]), "r"(b[0]), "r"(b[1]));
}

// ---------------------------------------------------------------------------
// Kernel 0: X (fp32) -> g_Xh (fp16 RN). 8 elems/thread, 16B stores.
// ---------------------------------------------------------------------------
__global__ __launch_bounds__(256)
void convert_X(const float* __restrict__ X) {
    size_t i = ((size_t)blockIdx.x * 256 + threadIdx.x) * 8;
    float4 v0 = *(const float4*)(X + i);
    float4 v1 = *(const float4*)(X + i + 4);
    __half2 h[4];
    h[0] = __floats2half2_rn(v0.x, v0.y);
    h[1] = __floats2half2_rn(v0.z, v0.w);
    h[2] = __floats2half2_rn(v1.x, v1.y);
    h[3] = __floats2half2_rn(v1.z, v1.w);
    *(uint4*)(g_Xh + i) = *(uint4*)h;
}

// ---------------------------------------------------------------------------
// Kernel 1 (fused): per 64x64 tile of Et, fold TT cores (tiny, redundant per
// block), emit Et[o][d] = fp16_rn( W[o][d] + ALPHA * Left[d,:]@Right[:,o] ).
// ---------------------------------------------------------------------------
__global__ __launch_bounds__(256)
void build_E_fused(const float* __restrict__ W,
                   const float* __restrict__ c0, const float* __restrict__ c1,
                   const float* __restrict__ c2, const float* __restrict__ c3,
                   const float* __restrict__ c4, const float* __restrict__ c5) {
    __shared__ float C0[64], C1[1024], C2[512], C3[512], C4[1024], C5[64];
    __shared__ float P[1024], S1[1024];
    __shared__ float Lt[64 * 8], Rt[8 * 64];
    const int t  = threadIdx.x;
    const int bd = blockIdx.x;    // d-tile (64 wide)
    const int bo = blockIdx.y;    // o-tile (64 wide)

    for (int i = t; i < 64;   i += 256) C0[i] = c0[i];
    for (int i = t; i < 1024; i += 256) C1[i] = c1[i];
    for (int i = t; i < 512;  i += 256) C2[i] = c2[i];
    for (int i = t; i < 512;  i += 256) C3[i] = c3[i];
    for (int i = t; i < 1024; i += 256) C4[i] = c4[i];
    for (int i = t; i < 64;   i += 256) C5[i] = c5[i];
    __syncthreads();

    #pragma unroll
    for (int p = 0; p < 4; p++) {
        int i = t + p * 256;
        int b = i & 7, m2 = (i >> 3) & 15, m1 = i >> 7;
        float s = 0.f;
        #pragma unroll
        for (int a = 0; a < 8; a++) s += C0[m1 * 8 + a] * C1[(a * 16 + m2) * 8 + b];
        P[i] = s;
    }
    #pragma unroll
    for (int p = 0; p < 4; p++) {
        int i = t + p * 256;
        int n3 = i & 7, n2 = (i >> 3) & 15, e = i >> 7;
        float s = 0.f;
        #pragma unroll
        for (int f = 0; f < 8; f++) s += C4[(e * 16 + n2) * 8 + f] * C5[f * 8 + n3];
        S1[i] = s;
    }
    __syncthreads();

    #pragma unroll
    for (int p = 0; p < 2; p++) {   // Left rows for this d-tile: 64x8
        int j = t + p * 256;
        int di = j >> 3, c = j & 7;
        int d = bd * 64 + di;
        int m1 = d & 7, m2 = (d >> 3) & 15, m3 = d >> 7;
        float s = 0.f;
        #pragma unroll
        for (int b = 0; b < 8; b++) s += P[(m1 * 16 + m2) * 8 + b] * C2[(b * 8 + m3) * 8 + c];
        Lt[di * 8 + c] = s;
    }
    #pragma unroll
    for (int p = 0; p < 2; p++) {   // Right cols for this o-tile: 8x64
        int j = t + p * 256;
        int c = j >> 6, oi = j & 63;
        int o = bo * 64 + oi;
        int n3 = o & 7, n2 = (o >> 3) & 15, n1 = o >> 7;
        float s = 0.f;
        #pragma unroll
        for (int e = 0; e < 8; e++) s += C3[(c * 8 + n1) * 8 + e] * S1[(e * 16 + n2) * 8 + n3];
        Rt[c * 64 + oi] = s;
    }
    __syncthreads();

    #pragma unroll
    for (int p = 0; p < 16; p++) {
        int j = t + p * 256;
        int di = j & 63, oi = j >> 6;        // di fastest -> coalesced
        float s = 0.f;
        #pragma unroll
        for (int c = 0; c < 8; c++) s += Lt[di * 8 + c] * Rt[c * 64 + oi];
        size_t idx = (size_t)(bo * 64 + oi) * 1024 + bd * 64 + di;
        g_Eh[idx] = __float2half_rn(W[idx] + ALPHA * s);
    }
}

// ---------------------------------------------------------------------------
// Kernel 2: fp16 mma.sync (m16n8k16) GEMM. C = Xh @ Eth^T + bias, fp32 accum.
// BM=128, BN=128, BK=64 (16 chunks). 256 threads, 8 warps (4x2), warp 32x64.
// 2 CTAs/SM. 3-stage cp.async pipeline, one sync per chunk.
// ldmatrix x4 fragment gathers; row stride 72 halves = 144B -> the 8 rows of
// each LDSM phase hit 8 distinct 16B lines (144*r mod 128 spans all) -> c-free.
// ---------------------------------------------------------------------------
#define TSTRIDE 72                 // halves per row (64 + 8 pad)
#define T_STG   (128 * TSTRIDE)    // halves per tile per stage
#define STAGES  3
#define NCHUNK  16

__global__ __launch_bounds__(256, 2)
void gemm_f16(const float* __restrict__ bias, float* __restrict__ out) {
    extern __shared__ __half smh[];
    __half* As = smh;                       // STAGES x [128][72]
    __half* Bs = smh + STAGES * T_STG;      // STAGES x [128][72] (Et rows = n)

    const int t    = threadIdx.x;
    const int wid  = t >> 5;
    const int lane = t & 31;
    const int g    = lane >> 2;     // 0..7
    const int tig  = lane & 3;      // 0..3
    const int wm   = wid >> 1;      // 0..3  (32-row band)
    const int wn   = wid & 1;       // 0..1  (64-col band)
    const int bx   = blockIdx.x;    // N tile (0..7)
    const int by   = blockIdx.y;    // M tile (0..127)

    const __half* Xb = g_Xh + (size_t)(by * 128) * 1024;
    const __half* Eb = g_Eh + (size_t)(bx * 128) * 1024;

    const uint32_t As_u = smem_u32(As);
    const uint32_t Bs_u = smem_u32(Bs);

    // A x4 tiles: (r0-7,kLo)(r8-15,kLo)(r0-7,kHi)(r8-15,kHi) -> a0..a3.
    // lanes 0-15: rows base+(lane&15), k-lo 16B; lanes 16-31: same rows, k-hi.
    uint32_t aoff[2];
    #pragma unroll
    for (int mt = 0; mt < 2; mt++) {
        int row = wm * 32 + mt * 16 + (lane & 15);
        int kh  = (lane >> 4) & 1;
        aoff[mt] = (uint32_t)(row * TSTRIDE) * 2u + (uint32_t)kh * 16u;
    }
    // B x4 tiles: (nLo,kLo)(nLo,kHi)(nHi,kLo)(nHi,kHi) -> bf0..bf3;
    // fragment for n-lo = {bf0,bf1}, n-hi = {bf2,bf3}.
    uint32_t boff[4];
    #pragma unroll
    for (int q = 0; q < 4; q++) {
        int row = wn * 64 + q * 16 + ((lane >> 4) & 1) * 8 + (lane & 7);
        int kh  = (lane >> 3) & 1;
        boff[q] = (uint32_t)(row * TSTRIDE) * 2u + (uint32_t)kh * 16u;
    }

    float acc[2][8][4];
    #pragma unroll
    for (int mt = 0; mt < 2; mt++)
        #pragma unroll
        for (int nt = 0; nt < 8; nt++)
            #pragma unroll
            for (int i = 0; i < 4; i++) acc[mt][nt][i] = 0.f;

    auto load_stage = [&](int s, int kc) {
        __half* Ad = As + s * T_STG;
        __half* Bd = Bs + s * T_STG;
        #pragma unroll
        for (int p = 0; p < 4; p++) {           // A: 128 rows x 64 halves
            int qi = t + p * 256;
            int row = qi >> 3, quad = qi & 7;   // 8 x 16B granules per row
            cp16(Ad + row * TSTRIDE + quad * 8,
                 Xb + (size_t)row * 1024 + kc + quad * 8);
        }
        #pragma unroll
        for (int p = 0; p < 4; p++) {           // B: 128 n-rows x 64 halves
            int qi = t + p * 256;
            int row = qi >> 3, quad = qi & 7;
            cp16(Bd + row * TSTRIDE + quad * 8,
                 Eb + (size_t)row * 1024 + kc + quad * 8);
        }
    };

    load_stage(0, 0);  CP_COMMIT();
    load_stage(1, 64); CP_COMMIT();

    for (int c = 0; c < NCHUNK; c++) {
        if (c == NCHUNK - 1) { CP_WAIT(0); } else { CP_WAIT(1); }
        __syncthreads();

        if (c + 2 < NCHUNK) {
            load_stage((c + 2) % STAGES, (c + 2) * 64);
            CP_COMMIT();
        }

        const uint32_t aB = As_u + (uint32_t)((c % STAGES) * T_STG) * 2u;
        const uint32_t bB = Bs_u + (uint32_t)((c % STAGES) * T_STG) * 2u;

        #pragma unroll
        for (int ks = 0; ks < 4; ks++) {              // 4 x k16
            const uint32_t kb = (uint32_t)ks * 32u;   // 16 halves = 32B
            uint32_t af[2][4];
            ldsm4(af[0][0], af[0][1], af[0][2], af[0][3], aB + aoff[0] + kb);
            ldsm4(af[1][0], af[1][1], af[1][2], af[1][3], aB + aoff[1] + kb);
            #pragma unroll
            for (int q = 0; q < 4; q++) {
                uint32_t bf[4];
                ldsm4(bf[0], bf[1], bf[2], bf[3], bB + boff[q] + kb);
                mma_f16(acc[0][2 * q],     af[0], bf);
                mma_f16(acc[1][2 * q],     af[1], bf);
                mma_f16(acc[0][2 * q + 1], af[0], bf + 2);
                mma_f16(acc[1][2 * q + 1], af[1], bf + 2);
            }
        }
    }

    // ---- epilogue: bias add, direct stores ----
    #pragma unroll
    for (int mt = 0; mt < 2; mt++) {
        int row0 = by * 128 + wm * 32 + mt * 16 + g;
        #pragma unroll
        for (int nt = 0; nt < 8; nt++) {
            int col = bx * 128 + wn * 64 + nt * 8 + tig * 2;
            float b0 = bias[col], b1 = bias[col + 1];
            float2 v0 = { acc[mt][nt][0] + b0, acc[mt][nt][1] + b1 };
            float2 v1 = { acc[mt][nt][2] + b0, acc[mt][nt][3] + b1 };
            *(float2*)(out + (size_t)row0 * 1024 + col)       = v0;
            *(float2*)(out + (size_t)(row0 + 8) * 1024 + col) = v1;
        }
    }
}

// ---------------------------------------------------------------------------
extern "C" void kernel_launch(void* const* d_in, const int* in_sizes, int n_in,
                              void* d_out, int out_size) {
    const float* x  = (const float*)d_in[0];
    const float* W  = (const float*)d_in[1];
    const float* b  = (const float*)d_in[2];
    const float* c0 = (const float*)d_in[3];
    const float* c1 = (const float*)d_in[4];
    const float* c2 = (const float*)d_in[5];
    const float* c3 = (const float*)d_in[6];
    const float* c4 = (const float*)d_in[7];
    const float* c5 = (const float*)d_in[8];
    float* out = (float*)d_out;

    convert_X<<<(MROWS * DDIM) / (256 * 8), 256>>>(x);

    dim3 bgrid(16, 16);
    build_E_fused<<<bgrid, 256>>>(W, c0, c1, c2, c3, c4, c5);

    const int smem_bytes = STAGES * 2 * T_STG * 2;   // 108 KB/CTA -> 2 CTAs/SM
    cudaFuncSetAttribute(gemm_f16, cudaFuncAttributeMaxDynamicSharedMemorySize, smem_bytes);
    dim3 grid(8, 128);   // bx fastest: concurrent CTAs share the A band in L2
    gemm_f16<<<grid, 256, smem_bytes>>>(b, out);
}

// round 11
// speedup vs baseline: 2.1269x; 1.0357x over previous
#include <cuda_runtime.h>
#include <cuda_fp16.h>
#include <cstdint>

#define ALPHA 16.0f
#define DDIM  1024
#define MROWS 16384   // B*S

// ---------------- scratch (no cudaMalloc allowed) ----------------
__device__ __align__(16) __half g_Eh[DDIM * DDIM];           // Et[o][d], fp16(RN)
__device__ __align__(16) __half g_Xh[(size_t)MROWS * DDIM];  // X in fp16(RN)

// ---------------- helpers ----------------
__device__ __forceinline__ uint32_t smem_u32(const void* p) {
    uint32_t a;
    asm("{ .reg .u64 t; cvta.to.shared.u64 t, %1; cvt.u32.u64 %0, t; }" : "=r"(a) : "l"(p));
    return a;
}
__device__ __forceinline__ void cp16(void* dst_smem, const void* src) {
    uint32_t d = smem_u32(dst_smem);
    asm volatile("cp.async.cg.shared.global [%0], [%1], 16;" :: "r"(d), "l"(src) : "memory");
}
#define CP_COMMIT()  asm volatile("cp.async.commit_group;" ::: "memory")
#define CP_WAIT(n)   asm volatile("cp.async.wait_group %0;" :: "n"(n) : "memory")

__device__ __forceinline__ void ldsm4(uint32_t& r0, uint32_t& r1, uint32_t& r2,
                                      uint32_t& r3, uint32_t addr) {
    asm volatile("ldmatrix.sync.aligned.m8n8.x4.shared.b16 {%0,%1,%2,%3}, [%4];"
                 : "=r"(r0), "=r"(r1), "=r"(r2), "=r"(r3) : "r"(addr));
}

__device__ __forceinline__ void mma_f16(float* c, const uint32_t* a, const uint32_t* b) {
    asm volatile(
        "mma.sync.aligned.m16n8k16.row.col.f32.f16.f16.f32 "
        "{%0,%1,%2,%3}, {%4,%5,%6,%7}, {%8,%9}, {%0,%1,%2,%3};"
        : "+f"(c[0]), "+f"(c[1]), "+f"(c[2]), "+f"(c[3])
        : "r"(a[0]), "r"(a[1]), "r"(a[2]), "r"(a[3]), "r"(b[0]), "r"(b[1]));
}

// ---------------------------------------------------------------------------
// Kernel 1 (fused prep): blocks [0,256) build Et tiles; blocks [256,8448)
// convert X->fp16. Build (latency-bound) overlaps convert (DRAM-bound).
// ---------------------------------------------------------------------------
#define BUILD_BLOCKS 256
#define CONV_BLOCKS  8192   // (16384*1024)/(256*8)

__global__ __launch_bounds__(256)
void prep_fused(const float* __restrict__ X, const float* __restrict__ W,
                const float* __restrict__ c0, const float* __restrict__ c1,
                const float* __restrict__ c2, const float* __restrict__ c3,
                const float* __restrict__ c4, const float* __restrict__ c5) {
    const int t = threadIdx.x;

    if (blockIdx.x >= BUILD_BLOCKS) {
        // ---- convert part ----
        size_t i = ((size_t)(blockIdx.x - BUILD_BLOCKS) * 256 + t) * 8;
        float4 v0 = *(const float4*)(X + i);
        float4 v1 = *(const float4*)(X + i + 4);
        __half2 h[4];
        h[0] = __floats2half2_rn(v0.x, v0.y);
        h[1] = __floats2half2_rn(v0.z, v0.w);
        h[2] = __floats2half2_rn(v1.x, v1.y);
        h[3] = __floats2half2_rn(v1.z, v1.w);
        *(uint4*)(g_Xh + i) = *(uint4*)h;
        return;
    }

    // ---- build part: 64x64 tile of Et ----
    __shared__ float C0[64], C1[1024], C2[512], C3[512], C4[1024], C5[64];
    __shared__ float P[1024], S1[1024];
    __shared__ float Lt[64 * 8], Rt[8 * 64];
    const int bd = blockIdx.x & 15;          // d-tile (64 wide)
    const int bo = blockIdx.x >> 4;          // o-tile (64 wide)

    for (int i = t; i < 64;   i += 256) C0[i] = c0[i];
    for (int i = t; i < 1024; i += 256) C1[i] = c1[i];
    for (int i = t; i < 512;  i += 256) C2[i] = c2[i];
    for (int i = t; i < 512;  i += 256) C3[i] = c3[i];
    for (int i = t; i < 1024; i += 256) C4[i] = c4[i];
    for (int i = t; i < 64;   i += 256) C5[i] = c5[i];
    __syncthreads();

    #pragma unroll
    for (int p = 0; p < 4; p++) {
        int i = t + p * 256;
        int b = i & 7, m2 = (i >> 3) & 15, m1 = i >> 7;
        float s = 0.f;
        #pragma unroll
        for (int a = 0; a < 8; a++) s += C0[m1 * 8 + a] * C1[(a * 16 + m2) * 8 + b];
        P[i] = s;
    }
    #pragma unroll
    for (int p = 0; p < 4; p++) {
        int i = t + p * 256;
        int n3 = i & 7, n2 = (i >> 3) & 15, e = i >> 7;
        float s = 0.f;
        #pragma unroll
        for (int f = 0; f < 8; f++) s += C4[(e * 16 + n2) * 8 + f] * C5[f * 8 + n3];
        S1[i] = s;
    }
    __syncthreads();

    #pragma unroll
    for (int p = 0; p < 2; p++) {   // Left rows for this d-tile: 64x8
        int j = t + p * 256;
        int di = j >> 3, c = j & 7;
        int d = bd * 64 + di;
        int m1 = d & 7, m2 = (d >> 3) & 15, m3 = d >> 7;
        float s = 0.f;
        #pragma unroll
        for (int b = 0; b < 8; b++) s += P[(m1 * 16 + m2) * 8 + b] * C2[(b * 8 + m3) * 8 + c];
        Lt[di * 8 + c] = s;
    }
    #pragma unroll
    for (int p = 0; p < 2; p++) {   // Right cols for this o-tile: 8x64
        int j = t + p * 256;
        int c = j >> 6, oi = j & 63;
        int o = bo * 64 + oi;
        int n3 = o & 7, n2 = (o >> 3) & 15, n1 = o >> 7;
        float s = 0.f;
        #pragma unroll
        for (int e = 0; e < 8; e++) s += C3[(c * 8 + n1) * 8 + e] * S1[(e * 16 + n2) * 8 + n3];
        Rt[c * 64 + oi] = s;
    }
    __syncthreads();

    #pragma unroll
    for (int p = 0; p < 16; p++) {
        int j = t + p * 256;
        int di = j & 63, oi = j >> 6;        // di fastest -> coalesced
        float s = 0.f;
        #pragma unroll
        for (int c = 0; c < 8; c++) s += Lt[di * 8 + c] * Rt[c * 64 + oi];
        size_t idx = (size_t)(bo * 64 + oi) * 1024 + bd * 64 + di;
        g_Eh[idx] = __float2half_rn(W[idx] + ALPHA * s);
    }
}

// ---------------------------------------------------------------------------
// Kernel 2: fp16 mma.sync (m16n8k16) GEMM. C = Xh @ Eth^T + bias, fp32 accum.
// BM=128, BN=128, BK=64 (16 chunks). 256 threads, 8 warps (4x2), warp 32x64.
// 2 CTAs/SM. 3-stage cp.async pipeline, one sync per chunk.
// Per k16 step: ALL 6 LDSM.x4 issued back-to-back (independent; latency paid
// once), then 16 dependent MMAs as an uninterrupted HMMA burst.
// Row stride 72 halves = 144B -> 8 rows/phase hit 8 distinct 16B lines.
// ---------------------------------------------------------------------------
#define TSTRIDE 72                 // halves per row (64 + 8 pad)
#define T_STG   (128 * TSTRIDE)    // halves per tile per stage
#define STAGES  3
#define NCHUNK  16

__global__ __launch_bounds__(256, 2)
void gemm_f16(const float* __restrict__ bias, float* __restrict__ out) {
    extern __shared__ __half smh[];
    __half* As = smh;                       // STAGES x [128][72]
    __half* Bs = smh + STAGES * T_STG;      // STAGES x [128][72] (Et rows = n)

    const int t    = threadIdx.x;
    const int wid  = t >> 5;
    const int lane = t & 31;
    const int g    = lane >> 2;     // 0..7
    const int tig  = lane & 3;      // 0..3
    const int wm   = wid >> 1;      // 0..3  (32-row band)
    const int wn   = wid & 1;       // 0..1  (64-col band)
    const int bx   = blockIdx.x;    // N tile (0..7)
    const int by   = blockIdx.y;    // M tile (0..127)

    const __half* Xb = g_Xh + (size_t)(by * 128) * 1024;
    const __half* Eb = g_Eh + (size_t)(bx * 128) * 1024;

    const uint32_t As_u = smem_u32(As);
    const uint32_t Bs_u = smem_u32(Bs);

    // A x4 tiles: (r0-7,kLo)(r8-15,kLo)(r0-7,kHi)(r8-15,kHi) -> a0..a3.
    uint32_t aoff[2];
    #pragma unroll
    for (int mt = 0; mt < 2; mt++) {
        int row = wm * 32 + mt * 16 + (lane & 15);
        int kh  = (lane >> 4) & 1;
        aoff[mt] = (uint32_t)(row * TSTRIDE) * 2u + (uint32_t)kh * 16u;
    }
    // B x4 tiles: (nLo,kLo)(nLo,kHi)(nHi,kLo)(nHi,kHi) -> frags {b0,b1},{b2,b3}.
    uint32_t boff[4];
    #pragma unroll
    for (int q = 0; q < 4; q++) {
        int row = wn * 64 + q * 16 + ((lane >> 4) & 1) * 8 + (lane & 7);
        int kh  = (lane >> 3) & 1;
        boff[q] = (uint32_t)(row * TSTRIDE) * 2u + (uint32_t)kh * 16u;
    }

    float acc[2][8][4];
    #pragma unroll
    for (int mt = 0; mt < 2; mt++)
        #pragma unroll
        for (int nt = 0; nt < 8; nt++)
            #pragma unroll
            for (int i = 0; i < 4; i++) acc[mt][nt][i] = 0.f;

    auto load_stage = [&](int s, int kc) {
        __half* Ad = As + s * T_STG;
        __half* Bd = Bs + s * T_STG;
        #pragma unroll
        for (int p = 0; p < 4; p++) {           // A: 128 rows x 64 halves
            int qi = t + p * 256;
            int row = qi >> 3, quad = qi & 7;
            cp16(Ad + row * TSTRIDE + quad * 8,
                 Xb + (size_t)row * 1024 + kc + quad * 8);
        }
        #pragma unroll
        for (int p = 0; p < 4; p++) {           // B: 128 n-rows x 64 halves
            int qi = t + p * 256;
            int row = qi >> 3, quad = qi & 7;
            cp16(Bd + row * TSTRIDE + quad * 8,
                 Eb + (size_t)row * 1024 + kc + quad * 8);
        }
    };

    load_stage(0, 0);  CP_COMMIT();
    load_stage(1, 64); CP_COMMIT();

    for (int c = 0; c < NCHUNK; c++) {
        if (c == NCHUNK - 1) { CP_WAIT(0); } else { CP_WAIT(1); }
        __syncthreads();

        if (c + 2 < NCHUNK) {
            load_stage((c + 2) % STAGES, (c + 2) * 64);
            CP_COMMIT();
        }

        const uint32_t aB = As_u + (uint32_t)((c % STAGES) * T_STG) * 2u;
        const uint32_t bB = Bs_u + (uint32_t)((c % STAGES) * T_STG) * 2u;

        #pragma unroll
        for (int ks = 0; ks < 4; ks++) {              // 4 x k16
            const uint32_t kb = (uint32_t)ks * 32u;   // 16 halves = 32B
            // ---- all fragment loads up front (independent LDSMs) ----
            uint32_t af[2][4];
            uint32_t bf[4][4];
            ldsm4(af[0][0], af[0][1], af[0][2], af[0][3], aB + aoff[0] + kb);
            ldsm4(af[1][0], af[1][1], af[1][2], af[1][3], aB + aoff[1] + kb);
            #pragma unroll
            for (int q = 0; q < 4; q++)
                ldsm4(bf[q][0], bf[q][1], bf[q][2], bf[q][3], bB + boff[q] + kb);
            // ---- 16 MMAs, uninterrupted ----
            #pragma unroll
            for (int q = 0; q < 4; q++) {
                mma_f16(acc[0][2 * q],     af[0], bf[q]);
                mma_f16(acc[1][2 * q],     af[1], bf[q]);
                mma_f16(acc[0][2 * q + 1], af[0], bf[q] + 2);
                mma_f16(acc[1][2 * q + 1], af[1], bf[q] + 2);
            }
        }
    }

    // ---- epilogue: bias add, direct stores ----
    #pragma unroll
    for (int mt = 0; mt < 2; mt++) {
        int row0 = by * 128 + wm * 32 + mt * 16 + g;
        #pragma unroll
        for (int nt = 0; nt < 8; nt++) {
            int col = bx * 128 + wn * 64 + nt * 8 + tig * 2;
            float b0 = bias[col], b1 = bias[col + 1];
            float2 v0 = { acc[mt][nt][0] + b0, acc[mt][nt][1] + b1 };
            float2 v1 = { acc[mt][nt][2] + b0, acc[mt][nt][3] + b1 };
            *(float2*)(out + (size_t)row0 * 1024 + col)       = v0;
            *(float2*)(out + (size_t)(row0 + 8) * 1024 + col) = v1;
        }
    }
}

// ---------------------------------------------------------------------------
extern "C" void kernel_launch(void* const* d_in, const int* in_sizes, int n_in,
                              void* d_out, int out_size) {
    const float* x  = (const float*)d_in[0];
    const float* W  = (const float*)d_in[1];
    const float* b  = (const float*)d_in[2];
    const float* c0 = (const float*)d_in[3];
    const float* c1 = (const float*)d_in[4];
    const float* c2 = (const float*)d_in[5];
    const float* c3 = (const float*)d_in[6];
    const float* c4 = (const float*)d_in[7];
    const float* c5 = (const float*)d_in[8];
    float* out = (float*)d_out;

    prep_fused<<<BUILD_BLOCKS + CONV_BLOCKS, 256>>>(x, W, c0, c1, c2, c3, c4, c5);

    const int smem_bytes = STAGES * 2 * T_STG * 2;   // 108 KB/CTA -> 2 CTAs/SM
    cudaFuncSetAttribute(gemm_f16, cudaFuncAttributeMaxDynamicSharedMemorySize, smem_bytes);
    dim3 grid(8, 128);   // bx fastest: concurrent CTAs share the A band in L2
    gemm_f16<<<grid, 256, smem_bytes>>>(b, out);
}